// round 15
// baseline (speedup 1.0000x reference)
#include <cuda_runtime.h>
#include <cstdint>

// PixelShuffle (depth-to-space, R=2, feature-major grouping)
// in : [B=8, X=256, Y=256, C=256] fp32,  C = F*4, c = f*4 + i*2 + j
// out: [B=8, 2X=512, 2Y=512, F=64] fp32
// out[b, 2x+i, 2y+j, f] = in[b, x, y, 4f + 2i + j]
//
// Each thread handles 4 consecutive features (f0 = 4*fg) of one pixel:
//   - 4 consecutive float4 loads (64 B contiguous per thread, MLP=4)
//   - register 4x4 transpose (free: compile-time component selection)
//   - 4 float4 stores, one per output quadrant, 16 B aligned & coalesced
//
// R13 confirmed this config at the HBM wall (158.2us, DRAM 85.6%). Single
// variable this round: block 256 -> 128 (same mapping, same total threads).
// Halves the per-CTA work quantum -> finer wave balance, smaller per-CTA
// front-batched LDG burst (16 vs 32 lines at occ-edge), shorter完 tail.

static constexpr int B = 8;
static constexpr int X = 256;
static constexpr int Y = 256;
static constexpr int F = 64;

__global__ __launch_bounds__(128, 16)
void pixel_shuffle_kernel(const float4* __restrict__ in, float4* __restrict__ out) {
    // tid layout: fg fastest (4 bits: f-group of 4 features), then y (8), x (8), b (3)
    const uint32_t tid = blockIdx.x * 128u + threadIdx.x;   // < B*X*Y*(F/4) = 8,388,608

    const uint32_t fg  = tid & 15u;           // f0 = 4*fg
    const uint32_t pix = tid >> 4;            // (b*X + x)*Y + y
    const uint32_t y   = pix & 255u;
    const uint32_t x   = (pix >> 8) & 255u;
    const uint32_t b   = pix >> 16;

    // Input (float4 units): pix*64 + 4*fg + k, k = 0..3. 64 B contiguous per thread.
    const float4* src = in + (pix << 6) + (fg << 2);
    const float4 v0 = __ldcs(src + 0);   // feature f0+0: (q00, q01, q10, q11)
    const float4 v1 = __ldcs(src + 1);   // feature f0+1
    const float4 v2 = __ldcs(src + 2);   // feature f0+2
    const float4 v3 = __ldcs(src + 3);   // feature f0+3

    // Output base (float4 units): ((b*512 + 2x)*512 + 2y)*16 + fg.
    const uint32_t base00_f4 = (((((b << 9) + (x << 1)) << 9) | (y << 1)) << 4) + fg;
    const uint32_t rowStride_f4 = 512u * 16u;   // 512*64 floats / 4

    // Quadrant (i=0,j=0): component .x of each feature
    __stcs(out + base00_f4,                        make_float4(v0.x, v1.x, v2.x, v3.x));
    // Quadrant (i=0,j=1): +64 floats = +16 float4
    __stcs(out + base00_f4 + 16u,                  make_float4(v0.y, v1.y, v2.y, v3.y));
    // Quadrant (i=1,j=0): +1 output row
    __stcs(out + base00_f4 + rowStride_f4,         make_float4(v0.z, v1.z, v2.z, v3.z));
    // Quadrant (i=1,j=1)
    __stcs(out + base00_f4 + rowStride_f4 + 16u,   make_float4(v0.w, v1.w, v2.w, v3.w));
}

extern "C" void kernel_launch(void* const* d_in, const int* in_sizes, int n_in,
                              void* d_out, int out_size) {
    const float4* in  = (const float4*)d_in[0];
    float4*       out = (float4*)d_out;

    const uint32_t total  = (uint32_t)B * X * Y * (F / 4);   // 8,388,608 threads
    const uint32_t blocks = total / 128u;                    // 65,536
    pixel_shuffle_kernel<<<blocks, 128>>>(in, out);
}

// round 17
// speedup vs baseline: 1.0085x; 1.0085x over previous
#include <cuda_runtime.h>
#include <cstdint>

// PixelShuffle (depth-to-space, R=2, feature-major grouping) — FINAL
// in : [B=8, X=256, Y=256, C=256] fp32,  C = F*4, c = f*4 + i*2 + j
// out: [B=8, 2X=512, 2Y=512, F=64] fp32
// out[b, 2x+i, 2y+j, f] = in[b, x, y, 4f + 2i + j]
//
// Each thread handles 4 consecutive features (f0 = 4*fg) of one pixel:
//   - 4 consecutive float4 loads (64 B contiguous per thread, MLP=4)
//   - register 4x4 transpose (free: compile-time component selection)
//   - 4 float4 stores, one per output quadrant, 16 B aligned & coalesced
//
// Session conclusion: kernel is at the mixed-R/W HBM roofline (~6.8 TB/s
// achieved, 85-86% of 8 TB/s spec). Four thread-geometries (1f/thread scalar
// stores; 4f/thread blk256; 4f/thread blk128; 8-load y-pair) all saturate at
// the same bandwidth except the y-pair variant which regressed (-10%).
// Traffic is minimal (each byte moved exactly once, all accesses full-sector),
// compute pipes idle. Locking in the best-profiled config (R13: DRAM 86.2%).

static constexpr int B = 8;
static constexpr int X = 256;
static constexpr int Y = 256;
static constexpr int F = 64;

__global__ __launch_bounds__(256, 8)
void pixel_shuffle_kernel(const float4* __restrict__ in, float4* __restrict__ out) {
    // tid layout: fg fastest (4 bits: f-group of 4 features), then y (8), x (8), b (3)
    const uint32_t tid = blockIdx.x * 256u + threadIdx.x;   // < B*X*Y*(F/4) = 8,388,608

    const uint32_t fg  = tid & 15u;           // f0 = 4*fg
    const uint32_t pix = tid >> 4;            // (b*X + x)*Y + y
    const uint32_t y   = pix & 255u;
    const uint32_t x   = (pix >> 8) & 255u;
    const uint32_t b   = pix >> 16;

    // Input (float4 units): pix*64 + 4*fg + k, k = 0..3. 64 B contiguous per thread.
    const float4* src = in + (pix << 6) + (fg << 2);
    const float4 v0 = __ldcs(src + 0);   // feature f0+0: (q00, q01, q10, q11)
    const float4 v1 = __ldcs(src + 1);   // feature f0+1
    const float4 v2 = __ldcs(src + 2);   // feature f0+2
    const float4 v3 = __ldcs(src + 3);   // feature f0+3

    // Output base (float4 units): ((b*512 + 2x)*512 + 2y)*16 + fg.
    const uint32_t base00_f4 = (((((b << 9) + (x << 1)) << 9) | (y << 1)) << 4) + fg;
    const uint32_t rowStride_f4 = 512u * 16u;   // 512*64 floats / 4

    // Quadrant (i=0,j=0): component .x of each feature
    __stcs(out + base00_f4,                        make_float4(v0.x, v1.x, v2.x, v3.x));
    // Quadrant (i=0,j=1): +64 floats = +16 float4
    __stcs(out + base00_f4 + 16u,                  make_float4(v0.y, v1.y, v2.y, v3.y));
    // Quadrant (i=1,j=0): +1 output row
    __stcs(out + base00_f4 + rowStride_f4,         make_float4(v0.z, v1.z, v2.z, v3.z));
    // Quadrant (i=1,j=1)
    __stcs(out + base00_f4 + rowStride_f4 + 16u,   make_float4(v0.w, v1.w, v2.w, v3.w));
}

extern "C" void kernel_launch(void* const* d_in, const int* in_sizes, int n_in,
                              void* d_out, int out_size) {
    const float4* in  = (const float4*)d_in[0];
    float4*       out = (float4*)d_out;

    const uint32_t total  = (uint32_t)B * X * Y * (F / 4);   // 8,388,608 threads
    const uint32_t blocks = total / 256u;                    // 32,768
    pixel_shuffle_kernel<<<blocks, 256>>>(in, out);
}